// round 2
// baseline (speedup 1.0000x reference)
#include <cuda_runtime.h>
#include <math.h>

#define NN 1024
#define ROWS_PER_BLK 2
#define THREADS (64 * ROWS_PER_BLK)

__device__ __forceinline__ float2 lerp2(float2 a, float2 b, float p) {
    return make_float2(fmaf(p, b.x - a.x, a.x), fmaf(p, b.y - a.y, a.y));
}
__device__ __forceinline__ float2 shfl2(float2 v, int lane) {
    float2 r;
    r.x = __shfl_sync(0xffffffffu, v.x, lane);
    r.y = __shfl_sync(0xffffffffu, v.y, lane);
    return r;
}
// y = a*x0 + b*x1 (complex)
__device__ __forceinline__ float2 cmuladd2(float2 a, float2 x0, float2 b, float2 x1) {
    float2 y;
    y.x = fmaf(a.x, x0.x, fmaf(-a.y, x0.y, fmaf(b.x, x1.x, -b.y * x1.y)));
    y.y = fmaf(a.x, x0.y, fmaf( a.y, x0.x, fmaf(b.x, x1.y,  b.y * x1.x)));
    return y;
}

// ---- thread-local perm factor, M in {4,8,16} ----
template<int M>
__device__ __forceinline__ void perm_local(float2* h, float p0, float p1, float p2) {
    float2 g[16];
#pragma unroll
    for (int b = 0; b < 16; b += M) {
#pragma unroll
        for (int j = 0; j < M; ++j) {
            int src = (j < M / 2) ? (2 * j) : (2 * (j - M / 2) + 1);
            g[b + j] = lerp2(h[b + j], h[b + src], p0);
        }
#pragma unroll
        for (int j = 0; j < M / 2; ++j)
            h[b + j] = lerp2(g[b + j], g[b + M / 2 - 1 - j], p1);
#pragma unroll
        for (int j = M / 2; j < M; ++j)
            h[b + j] = lerp2(g[b + j], g[b + 3 * M / 2 - 1 - j], p2);
    }
}

// ---- thread-local diag factor, M in {2,4,8,16} ----
template<int M>
__device__ __forceinline__ void diag_local(float2* h, const float2* __restrict__ A) {
#pragma unroll
    for (int k = 0; k < M / 2; ++k) {
        float2 A00 = __ldg(A + k);
        float2 A01 = __ldg(A + (M / 2) + k);
        float2 A10 = __ldg(A + M + k);
        float2 A11 = __ldg(A + 3 * (M / 2) + k);
#pragma unroll
        for (int b = 0; b < 16; b += M) {
            float2 x0 = h[b + k], x1 = h[b + M / 2 + k];
            h[b + k]         = cmuladd2(A00, x0, A01, x1);
            h[b + M / 2 + k] = cmuladd2(A10, x0, A11, x1);
        }
    }
}

// ---- warp-level perm factor, M in {32..512} ----
template<int M>
__device__ __forceinline__ void perm_warp(float2* h, int lane, float p0, float p1, float p2) {
    constexpr int TB = M / 16;  // threads per block of M
    constexpr int HT = M / 32;  // threads per half
    int tprime = lane & (TB - 1);
    int blockbase = lane - tprime;
    int hb = (tprime >= HT) ? 1 : 0;
    int u = tprime & (HT - 1);
    int srcLo = blockbase + 2 * u;
    float pm = hb ? p2 : p1;
    float2 g[16];
#pragma unroll
    for (int e = 0; e < 8; ++e) {
        float2 v0 = shfl2(h[2 * e], srcLo);
        float2 v1 = shfl2(h[2 * e + 1], srcLo);
        float2 s = hb ? v1 : v0;
        g[e] = lerp2(h[e], s, p0);
    }
#pragma unroll
    for (int e = 8; e < 16; ++e) {
        float2 v0 = shfl2(h[2 * e - 16], srcLo + 1);
        float2 v1 = shfl2(h[2 * e - 15], srcLo + 1);
        float2 s = hb ? v1 : v0;
        g[e] = lerp2(h[e], s, p0);
    }
    int mirT = blockbase + hb * HT + (HT - 1 - u);
#pragma unroll
    for (int e = 0; e < 16; ++e) {
        float2 gm = shfl2(g[15 - e], mirT);
        h[e] = lerp2(g[e], gm, pm);
    }
}

// ---- warp-level diag factor, M in {32..512} ----
template<int M>
__device__ __forceinline__ void diag_warp(float2* h, int lane, const float2* __restrict__ A) {
    constexpr int TB = M / 16, HT = M / 32;
    int tprime = lane & (TB - 1);
    bool low = tprime < HT;
    int partner = lane + (low ? HT : -HT);
    int kbase = 16 * (tprime & (HT - 1));
    const float2* Ai0 = A + (low ? 0 : 2) * (M / 2) + kbase;
    const float2* Ai1 = Ai0 + (M / 2);
#pragma unroll
    for (int e = 0; e < 16; ++e) {
        float2 hp = shfl2(h[e], partner);
        float2 x0 = low ? h[e] : hp;
        float2 x1 = low ? hp : h[e];
        h[e] = cmuladd2(__ldg(Ai0 + e), x0, __ldg(Ai1 + e), x1);
    }
}

__global__ __launch_bounds__(THREADS) void butterfly_kernel(
    const float* __restrict__ x,
    const float* __restrict__ perm_logit,
    const float* __restrict__ abcd,
    const float* __restrict__ bvec,
    float* __restrict__ out)
{
    __shared__ float2 S[ROWS_PER_BLK][NN];  // staging for m=1024, layout [e*64 + t]

    const int tid = threadIdx.x;
    const int rloc = tid >> 6;
    const int t = tid & 63;        // thread within row
    const int lane = t & 31;       // lane within warp
    const long row = (long)blockIdx.x * ROWS_PER_BLK + rloc;
    float2* Sr = S[rloc];

    float2 h[16];
    const float4* xv = (const float4*)(x + row * NN + t * 16);
#pragma unroll
    for (int q = 0; q < 4; ++q) {
        float4 v = xv[q];
        h[4 * q + 0] = make_float2(v.x, 0.f);
        h[4 * q + 1] = make_float2(v.y, 0.f);
        h[4 * q + 2] = make_float2(v.z, 0.f);
        h[4 * q + 3] = make_float2(v.w, 0.f);
    }

#pragma unroll
    for (int d = 0; d < 2; ++d) {
        const float p0 = 1.0f / (1.0f + expf(-__ldg(perm_logit + 3 * d + 0)));
        const float p1 = 1.0f / (1.0f + expf(-__ldg(perm_logit + 3 * d + 1)));
        const float p2 = 1.0f / (1.0f + expf(-__ldg(perm_logit + 3 * d + 2)));
        const float2* Ab = (const float2*)abcd + d * 4092;

        // ---- perm: m = 4 .. 1024 ----
        perm_local<4>(h, p0, p1, p2);
        perm_local<8>(h, p0, p1, p2);
        perm_local<16>(h, p0, p1, p2);
        perm_warp<32>(h, lane, p0, p1, p2);
        perm_warp<64>(h, lane, p0, p1, p2);
        perm_warp<128>(h, lane, p0, p1, p2);
        perm_warp<256>(h, lane, p0, p1, p2);
        perm_warp<512>(h, lane, p0, p1, p2);
        {   // m = 1024: eo via smem (cross-warp), mirror via shfl (half == warp)
            __syncthreads();
#pragma unroll
            for (int e = 0; e < 16; ++e) Sr[e * 64 + t] = h[e];
            __syncthreads();
            const int hb = t >> 5;
            const float pm = hb ? p2 : p1;
            float2 g[16];
#pragma unroll
            for (int e = 0; e < 8; ++e)
                g[e] = lerp2(h[e], Sr[(2 * e + hb) * 64 + 2 * lane], p0);
#pragma unroll
            for (int e = 8; e < 16; ++e)
                g[e] = lerp2(h[e], Sr[(2 * e - 16 + hb) * 64 + 2 * lane + 1], p0);
#pragma unroll
            for (int e = 0; e < 16; ++e) {
                float2 gm = shfl2(g[15 - e], 31 - lane);
                h[e] = lerp2(g[e], gm, pm);
            }
        }

        // ---- diag: m = 2 .. 1024; coefficient offset doff(M) = 4096 - 4M ----
        diag_local<2>(h, Ab + 4096 - 8);
        diag_local<4>(h, Ab + 4096 - 16);
        diag_local<8>(h, Ab + 4096 - 32);
        diag_local<16>(h, Ab + 4096 - 64);
        diag_warp<32>(h, lane, Ab + 4096 - 128);
        diag_warp<64>(h, lane, Ab + 4096 - 256);
        diag_warp<128>(h, lane, Ab + 4096 - 512);
        diag_warp<256>(h, lane, Ab + 4096 - 1024);
        diag_warp<512>(h, lane, Ab + 4096 - 2048);
        {   // m = 1024: partner is same lane in other warp, via smem
            __syncthreads();
#pragma unroll
            for (int e = 0; e < 16; ++e) Sr[e * 64 + t] = h[e];
            __syncthreads();
            const bool low = t < 32;
            const int partner = t ^ 32;
            const float2* Ai0 = Ab + (low ? 0 : 2) * 512 + 16 * lane;
            const float2* Ai1 = Ai0 + 512;
#pragma unroll
            for (int e = 0; e < 16; ++e) {
                float2 hp = Sr[e * 64 + partner];
                float2 x0 = low ? h[e] : hp;
                float2 x1 = low ? hp : h[e];
                h[e] = cmuladd2(__ldg(Ai0 + e), x0, __ldg(Ai1 + e), x1);
            }
        }
    }

    // out = b + Re(h)
    float4* ov = (float4*)(out + row * NN + t * 16);
    const float4* bv = (const float4*)(bvec + t * 16);
#pragma unroll
    for (int q = 0; q < 4; ++q) {
        float4 bb = __ldg(bv + q);
        float4 o;
        o.x = bb.x + h[4 * q + 0].x;
        o.y = bb.y + h[4 * q + 1].x;
        o.z = bb.z + h[4 * q + 2].x;
        o.w = bb.w + h[4 * q + 3].x;
        ov[q] = o;
    }
}

extern "C" void kernel_launch(void* const* d_in, const int* in_sizes, int n_in,
                              void* d_out, int out_size) {
    const float* x          = (const float*)d_in[0];
    const float* perm_logit = (const float*)d_in[1];
    const float* abcd       = (const float*)d_in[2];
    const float* bvec       = (const float*)d_in[3];
    float* out = (float*)d_out;
    const int B = in_sizes[0] / NN;
    butterfly_kernel<<<B / ROWS_PER_BLK, THREADS>>>(x, perm_logit, abcd, bvec, out);
}

// round 6
// speedup vs baseline: 3.7442x; 3.7442x over previous
#include <cuda_runtime.h>
#include <cstdint>
#include <math.h>

#define NN 1024
#define BB 16384

// ---------------- scratch (static device memory; no allocation) --------------
__device__ float g_G[NN * NN];    // G[j][i] = butterfly(e_j)[i]
__device__ float g_Bt[NN * NN];   // Bt[n][k] = G[k][n], tf32(RN)-rounded

// ============================================================================
// Kernel 1: butterfly applied to identity rows -> G  (Round-1 verified core)
// ============================================================================
__device__ __forceinline__ float2 lerp2(float2 a, float2 b, float p) {
    return make_float2(fmaf(p, b.x - a.x, a.x), fmaf(p, b.y - a.y, a.y));
}

__global__ __launch_bounds__(256) void butterfly_identity_kernel(
    const float* __restrict__ perm_logit,
    const float* __restrict__ abcd)
{
    __shared__ float2 buf0[NN];
    __shared__ float2 buf1[NN];

    const int tid = threadIdx.x;
    const int row = blockIdx.x;   // identity column j

#pragma unroll
    for (int k = 0; k < 4; ++k) {
        int t = tid + 256 * k;
        buf0[t] = make_float2(t == row ? 1.0f : 0.0f, 0.0f);
    }
    __syncthreads();

    float2* cur = buf0;
    float2* nxt = buf1;

    for (int d = 0; d < 2; ++d) {
        const float p0 = 1.0f / (1.0f + expf(-perm_logit[d * 3 + 0]));
        const float p1 = 1.0f / (1.0f + expf(-perm_logit[d * 3 + 1]));
        const float p2 = 1.0f / (1.0f + expf(-perm_logit[d * 3 + 2]));

#pragma unroll
        for (int s = 0; s < 9; ++s) {
            const int half  = 2 << s;
            const int quart = 1 << s;
#pragma unroll
            for (int qq = 0; qq < 2; ++qq) {
                const int q   = tid + qq * 256;
                const int blk = q >> (s + 1);
                const int w   = q & (half - 1);
                const int hh  = w >> s;
                const int j   = w & (quart - 1);
                const int base = blk << (s + 2);
                const int pa = hh * half + j;
                const int pb = hh * half + (half - 1 - j);
                const int ea = (pa < half) ? (2 * pa) : (2 * (pa - half) + 1);
                const int eb = (pb < half) ? (2 * pb) : (2 * (pb - half) + 1);
                float2 ha  = cur[base + pa];
                float2 hea = cur[base + ea];
                float2 hb  = cur[base + pb];
                float2 heb = cur[base + eb];
                float2 ga = lerp2(ha, hea, p0);
                float2 gb = lerp2(hb, heb, p0);
                const float pm = hh ? p2 : p1;
                nxt[base + pa] = lerp2(ga, gb, pm);
                nxt[base + pb] = lerp2(gb, ga, pm);
            }
            __syncthreads();
            float2* tmp = cur; cur = nxt; nxt = tmp;
        }

        const int doffs[10] = {4088, 4080, 4064, 4032, 3968, 3840, 3584, 3072, 2048, 0};
#pragma unroll
        for (int s = 0; s < 10; ++s) {
            const int half = 1 << s;
            const float2* A = (const float2*)(abcd + (size_t)(d * 4092 + doffs[s]) * 2);
#pragma unroll
            for (int qq = 0; qq < 2; ++qq) {
                const int q   = tid + qq * 256;
                const int blk = q >> s;
                const int k   = q & (half - 1);
                const int t0  = (blk << (s + 1)) + k;
                const int t1  = t0 + half;
                float2 x0 = cur[t0];
                float2 x1 = cur[t1];
                float2 A00 = __ldg(&A[0 * half + k]);
                float2 A01 = __ldg(&A[1 * half + k]);
                float2 A10 = __ldg(&A[2 * half + k]);
                float2 A11 = __ldg(&A[3 * half + k]);
                float2 y0, y1;
                y0.x = fmaf(A00.x, x0.x, fmaf(-A00.y, x0.y, fmaf(A01.x, x1.x, -A01.y * x1.y)));
                y0.y = fmaf(A00.x, x0.y, fmaf( A00.y, x0.x, fmaf(A01.x, x1.y,  A01.y * x1.x)));
                y1.x = fmaf(A10.x, x0.x, fmaf(-A10.y, x0.y, fmaf(A11.x, x1.x, -A11.y * x1.y)));
                y1.y = fmaf(A10.x, x0.y, fmaf( A10.y, x0.x, fmaf(A11.x, x1.y,  A11.y * x1.x)));
                nxt[t0] = y0;
                nxt[t1] = y1;
            }
            __syncthreads();
            float2* tmp = cur; cur = nxt; nxt = tmp;
        }
    }

#pragma unroll
    for (int k = 0; k < 4; ++k) {
        int t = tid + 256 * k;
        g_G[(size_t)row * NN + t] = cur[t].x;
    }
}

// ============================================================================
// Kernel 2: transpose G -> Bt (tf32 RN-rounded).  Bt[n][k] = G[k][n]
// ============================================================================
__device__ __forceinline__ float tf32_rna(float f) {
    uint32_t u;
    asm("cvt.rna.tf32.f32 %0, %1;" : "=r"(u) : "f"(f));
    return __uint_as_float(u);
}

__global__ __launch_bounds__(256) void transpose_round_kernel()
{
    __shared__ float tl[32][33];
    const int tx = threadIdx.x & 31;
    const int ty = threadIdx.x >> 5;       // 0..7
    const int k0 = blockIdx.x * 32;
    const int n0 = blockIdx.y * 32;
#pragma unroll
    for (int i = 0; i < 32; i += 8)
        tl[ty + i][tx] = g_G[(size_t)(k0 + ty + i) * NN + n0 + tx];
    __syncthreads();
#pragma unroll
    for (int i = 0; i < 32; i += 8) {
        const int n = n0 + ty + i;
        const int k = k0 + tx;
        g_Bt[(size_t)n * NN + k] = tf32_rna(tl[tx][ty + i]);
    }
}

// ============================================================================
// Kernel 3: tf32 mma.sync GEMM   out[r][n] = sum_k x[r][k]*Bt[n][k] + b[n]
//   BM=128 BN=128 BK=32, 256 thr (warp grid 2x4, warp tile 64x32),
//   3-stage cp.async pipeline, padded smem stride 36 floats.
// ============================================================================
#define BM 128
#define BN 128
#define BK 32
#define SA 36
#define STAGE_F (128 * SA * 2)       // A(128x36) + B(128x36) floats = 9216
#define NSTAGE 3
#define NCH (NN / BK)                // 32
#define DYN_SMEM (NSTAGE * STAGE_F * 4)   // 110592 B

__device__ __forceinline__ uint32_t smem_u32(const void* p) {
    uint32_t a;
    asm("{ .reg .u64 t; cvta.to.shared.u64 t, %1; cvt.u32.u64 %0, t; }" : "=r"(a) : "l"(p));
    return a;
}
__device__ __forceinline__ void cp_async16(uint32_t dst, const void* src) {
    asm volatile("cp.async.cg.shared.global [%0], [%1], 16;" :: "r"(dst), "l"(src));
}
__device__ __forceinline__ void cp_commit() {
    asm volatile("cp.async.commit_group;" ::: "memory");
}
template<int N>
__device__ __forceinline__ void cp_wait() {
    asm volatile("cp.async.wait_group %0;" :: "n"(N) : "memory");
}
__device__ __forceinline__ uint32_t cvt_rna_u(float f) {
    uint32_t u;
    asm("cvt.rna.tf32.f32 %0, %1;" : "=r"(u) : "f"(f));
    return u;
}
__device__ __forceinline__ void mma_tf32(float* d, uint32_t a0, uint32_t a1,
                                         uint32_t a2, uint32_t a3,
                                         uint32_t b0, uint32_t b1) {
    asm volatile(
        "mma.sync.aligned.m16n8k8.row.col.f32.tf32.tf32.f32 "
        "{%0,%1,%2,%3}, {%4,%5,%6,%7}, {%8,%9}, {%0,%1,%2,%3};"
        : "+f"(d[0]), "+f"(d[1]), "+f"(d[2]), "+f"(d[3])
        : "r"(a0), "r"(a1), "r"(a2), "r"(a3), "r"(b0), "r"(b1));
}

__global__ __launch_bounds__(256, 1) void gemm_kernel(
    const float* __restrict__ x,
    const float* __restrict__ bvec,
    float* __restrict__ out)
{
    extern __shared__ float sm[];
    const int tid  = threadIdx.x;
    const int wid  = tid >> 5;
    const int lane = tid & 31;
    const int gid  = lane >> 2;   // group id (0..7)
    const int tg   = lane & 3;    // thread in group
    const int bn = blockIdx.x;    // 0..7
    const int bm = blockIdx.y;    // 0..127
    const int wm = wid & 1;       // warp row (0..1) -> 64 rows
    const int wn = wid >> 1;      // warp col (0..3) -> 32 cols

    const uint32_t sbase = smem_u32(sm);

    auto load_chunk = [&](int c, int s) {
        const uint32_t st = sbase + (uint32_t)(s * STAGE_F * 4);
#pragma unroll
        for (int i = 0; i < 8; ++i) {
            int o = tid + i * 256;
            if (o < 1024) {               // A tile
                int r = o >> 3, seg = o & 7;
                cp_async16(st + (uint32_t)(r * SA + seg * 4) * 4,
                           x + (size_t)(bm * BM + r) * NN + c * BK + seg * 4);
            } else {                      // B tile
                int o2 = o - 1024;
                int n = o2 >> 3, seg = o2 & 7;
                cp_async16(st + (uint32_t)(128 * SA + n * SA + seg * 4) * 4,
                           g_Bt + (size_t)(bn * BN + n) * NN + c * BK + seg * 4);
            }
        }
        cp_commit();
    };

    float acc[4][4][4];
#pragma unroll
    for (int mt = 0; mt < 4; ++mt)
#pragma unroll
        for (int nt = 0; nt < 4; ++nt)
#pragma unroll
            for (int r = 0; r < 4; ++r) acc[mt][nt][r] = 0.0f;

    load_chunk(0, 0);
    load_chunk(1, 1);

#pragma unroll 1
    for (int c = 0; c < NCH; ++c) {
        cp_wait<1>();
        __syncthreads();
        {   // prefetch chunk c+2 (clamped; redundant tail loads are harmless)
            int cn = (c + 2 < NCH) ? (c + 2) : (NCH - 1);
            load_chunk(cn, (c + 2) % NSTAGE);
        }
        const float* As = sm + (c % NSTAGE) * STAGE_F;
        const float* Bs = As + 128 * SA;

#pragma unroll
        for (int ks = 0; ks < 4; ++ks) {
            const int k0 = ks * 8;
            uint32_t breg[4][2];
#pragma unroll
            for (int nt = 0; nt < 4; ++nt) {
                const int cb = wn * 32 + nt * 8 + gid;
                breg[nt][0] = __float_as_uint(Bs[cb * SA + k0 + tg]);
                breg[nt][1] = __float_as_uint(Bs[cb * SA + k0 + tg + 4]);
            }
#pragma unroll
            for (int mt = 0; mt < 4; ++mt) {
                const int rb = wm * 64 + mt * 16 + gid;
                uint32_t a0 = cvt_rna_u(As[rb * SA + k0 + tg]);
                uint32_t a1 = cvt_rna_u(As[(rb + 8) * SA + k0 + tg]);
                uint32_t a2 = cvt_rna_u(As[rb * SA + k0 + tg + 4]);
                uint32_t a3 = cvt_rna_u(As[(rb + 8) * SA + k0 + tg + 4]);
#pragma unroll
                for (int nt = 0; nt < 4; ++nt)
                    mma_tf32(acc[mt][nt], a0, a1, a2, a3, breg[nt][0], breg[nt][1]);
            }
        }
    }

    // ---- epilogue: D + bias -> out ----
    const float* brow = bvec + bn * BN;
#pragma unroll
    for (int mt = 0; mt < 4; ++mt) {
#pragma unroll
        for (int h = 0; h < 2; ++h) {
            const int r = bm * BM + wm * 64 + mt * 16 + gid + h * 8;
            float* orow = out + (size_t)r * NN + bn * BN;
#pragma unroll
            for (int nt = 0; nt < 4; ++nt) {
                const int cc = wn * 32 + nt * 8 + tg * 2;
                float2 bb = __ldg((const float2*)(brow + cc));
                float2 o;
                o.x = acc[mt][nt][h * 2 + 0] + bb.x;
                o.y = acc[mt][nt][h * 2 + 1] + bb.y;
                *(float2*)(orow + cc) = o;
            }
        }
    }
}

// ============================================================================
extern "C" void kernel_launch(void* const* d_in, const int* in_sizes, int n_in,
                              void* d_out, int out_size) {
    const float* x          = (const float*)d_in[0];
    const float* perm_logit = (const float*)d_in[1];
    const float* abcd       = (const float*)d_in[2];
    const float* bvec       = (const float*)d_in[3];
    float* out = (float*)d_out;

    cudaFuncSetAttribute(gemm_kernel, cudaFuncAttributeMaxDynamicSharedMemorySize, DYN_SMEM);

    butterfly_identity_kernel<<<NN, 256>>>(perm_logit, abcd);
    {
        dim3 g(NN / 32, NN / 32);
        transpose_round_kernel<<<g, 256>>>();
    }
    {
        dim3 g(NN / BN, BB / BM);   // (8, 128): bn fastest for L2 reuse of A-wave
        gemm_kernel<<<g, 256, DYN_SMEM>>>(x, bvec, out);
    }
}

// round 7
// speedup vs baseline: 4.1518x; 1.1089x over previous
#include <cuda_runtime.h>
#include <cstdint>
#include <math.h>

#define NN 1024
#define BB 16384

// ---------------- scratch (static device memory; no allocation) --------------
__device__ float g_G[NN * NN];    // G[j][i] = butterfly(e_j)[i]
__device__ float g_Bt[NN * NN];   // Bt[n][k] = G[k][n], tf32(RNA)-rounded

// ============================================================================
// Kernel 1: butterfly applied to identity rows -> G  (512-thread version)
// ============================================================================
__device__ __forceinline__ float2 lerp2(float2 a, float2 b, float p) {
    return make_float2(fmaf(p, b.x - a.x, a.x), fmaf(p, b.y - a.y, a.y));
}

__global__ __launch_bounds__(512) void butterfly_identity_kernel(
    const float* __restrict__ perm_logit,
    const float* __restrict__ abcd)
{
    __shared__ float2 buf0[NN];
    __shared__ float2 buf1[NN];

    const int tid = threadIdx.x;
    const int row = blockIdx.x;   // identity column j

#pragma unroll
    for (int k = 0; k < 2; ++k) {
        int t = tid + 512 * k;
        buf0[t] = make_float2(t == row ? 1.0f : 0.0f, 0.0f);
    }
    __syncthreads();

    float2* cur = buf0;
    float2* nxt = buf1;

    for (int d = 0; d < 2; ++d) {
        const float p0 = 1.0f / (1.0f + expf(-perm_logit[d * 3 + 0]));
        const float p1 = 1.0f / (1.0f + expf(-perm_logit[d * 3 + 1]));
        const float p2 = 1.0f / (1.0f + expf(-perm_logit[d * 3 + 2]));

#pragma unroll
        for (int s = 0; s < 9; ++s) {
            const int half  = 2 << s;
            const int quart = 1 << s;
            const int q   = tid;                     // pair slot in [0,512)
            const int blk = q >> (s + 1);
            const int w   = q & (half - 1);
            const int hh  = w >> s;
            const int j   = w & (quart - 1);
            const int base = blk << (s + 2);
            const int pa = hh * half + j;
            const int pb = hh * half + (half - 1 - j);
            const int ea = (pa < half) ? (2 * pa) : (2 * (pa - half) + 1);
            const int eb = (pb < half) ? (2 * pb) : (2 * (pb - half) + 1);
            float2 ha  = cur[base + pa];
            float2 hea = cur[base + ea];
            float2 hb  = cur[base + pb];
            float2 heb = cur[base + eb];
            float2 ga = lerp2(ha, hea, p0);
            float2 gb = lerp2(hb, heb, p0);
            const float pm = hh ? p2 : p1;
            nxt[base + pa] = lerp2(ga, gb, pm);
            nxt[base + pb] = lerp2(gb, ga, pm);
            __syncthreads();
            float2* tmp = cur; cur = nxt; nxt = tmp;
        }

        const int doffs[10] = {4088, 4080, 4064, 4032, 3968, 3840, 3584, 3072, 2048, 0};
#pragma unroll
        for (int s = 0; s < 10; ++s) {
            const int half = 1 << s;
            const float2* A = (const float2*)(abcd + (size_t)(d * 4092 + doffs[s]) * 2);
            const int q   = tid;
            const int blk = q >> s;
            const int k   = q & (half - 1);
            const int t0  = (blk << (s + 1)) + k;
            const int t1  = t0 + half;
            float2 x0 = cur[t0];
            float2 x1 = cur[t1];
            float2 A00 = __ldg(&A[0 * half + k]);
            float2 A01 = __ldg(&A[1 * half + k]);
            float2 A10 = __ldg(&A[2 * half + k]);
            float2 A11 = __ldg(&A[3 * half + k]);
            float2 y0, y1;
            y0.x = fmaf(A00.x, x0.x, fmaf(-A00.y, x0.y, fmaf(A01.x, x1.x, -A01.y * x1.y)));
            y0.y = fmaf(A00.x, x0.y, fmaf( A00.y, x0.x, fmaf(A01.x, x1.y,  A01.y * x1.x)));
            y1.x = fmaf(A10.x, x0.x, fmaf(-A10.y, x0.y, fmaf(A11.x, x1.x, -A11.y * x1.y)));
            y1.y = fmaf(A10.x, x0.y, fmaf( A10.y, x0.x, fmaf(A11.x, x1.y,  A11.y * x1.x)));
            nxt[t0] = y0;
            nxt[t1] = y1;
            __syncthreads();
            float2* tmp = cur; cur = nxt; nxt = tmp;
        }
    }

#pragma unroll
    for (int k = 0; k < 2; ++k) {
        int t = tid + 512 * k;
        g_G[(size_t)row * NN + t] = cur[t].x;
    }
}

// ============================================================================
// Kernel 2: transpose G -> Bt (tf32 RNA-rounded).  Bt[n][k] = G[k][n]
// ============================================================================
__device__ __forceinline__ float tf32_rna(float f) {
    uint32_t u;
    asm("cvt.rna.tf32.f32 %0, %1;" : "=r"(u) : "f"(f));
    return __uint_as_float(u);
}

__global__ __launch_bounds__(256) void transpose_round_kernel()
{
    __shared__ float tl[32][33];
    const int tx = threadIdx.x & 31;
    const int ty = threadIdx.x >> 5;       // 0..7
    const int k0 = blockIdx.x * 32;
    const int n0 = blockIdx.y * 32;
#pragma unroll
    for (int i = 0; i < 32; i += 8)
        tl[ty + i][tx] = g_G[(size_t)(k0 + ty + i) * NN + n0 + tx];
    __syncthreads();
#pragma unroll
    for (int i = 0; i < 32; i += 8) {
        const int n = n0 + ty + i;
        const int k = k0 + tx;
        g_Bt[(size_t)n * NN + k] = tf32_rna(tl[tx][ty + i]);
    }
}

// ============================================================================
// Kernel 3: tf32 mma.sync GEMM   out[r][n] = sum_k x[r][k]*Bt[n][k] + b[n]
//   BM=128 BN=128 BK=32, 128 thr (warp grid 2x2, warp tile 64x64),
//   ldmatrix.x4 fragment loads, 3-stage cp.async pipeline, stride 36 floats.
// ============================================================================
#define BM 128
#define BN 128
#define BK 32
#define SA 36
#define STAGE_F (128 * SA * 2)       // A(128x36) + B(128x36) floats
#define NSTAGE 3
#define NCH (NN / BK)                // 32
#define DYN_SMEM (NSTAGE * STAGE_F * 4)

__device__ __forceinline__ uint32_t smem_u32(const void* p) {
    uint32_t a;
    asm("{ .reg .u64 t; cvta.to.shared.u64 t, %1; cvt.u32.u64 %0, t; }" : "=r"(a) : "l"(p));
    return a;
}
__device__ __forceinline__ void cp_async16(uint32_t dst, const void* src) {
    asm volatile("cp.async.cg.shared.global [%0], [%1], 16;" :: "r"(dst), "l"(src));
}
__device__ __forceinline__ void cp_commit() {
    asm volatile("cp.async.commit_group;" ::: "memory");
}
template<int N>
__device__ __forceinline__ void cp_wait() {
    asm volatile("cp.async.wait_group %0;" :: "n"(N) : "memory");
}
__device__ __forceinline__ uint32_t cvt_rna_u(uint32_t f) {
    uint32_t u;
    asm("cvt.rna.tf32.f32 %0, %1;" : "=r"(u) : "f"(__uint_as_float(f)));
    return u;
}
__device__ __forceinline__ void ldsm_x4(uint32_t* r, uint32_t addr) {
    asm volatile("ldmatrix.sync.aligned.m8n8.x4.shared.b16 {%0,%1,%2,%3}, [%4];"
                 : "=r"(r[0]), "=r"(r[1]), "=r"(r[2]), "=r"(r[3]) : "r"(addr));
}
__device__ __forceinline__ void mma_tf32(float* d, uint32_t a0, uint32_t a1,
                                         uint32_t a2, uint32_t a3,
                                         uint32_t b0, uint32_t b1) {
    asm volatile(
        "mma.sync.aligned.m16n8k8.row.col.f32.tf32.tf32.f32 "
        "{%0,%1,%2,%3}, {%4,%5,%6,%7}, {%8,%9}, {%0,%1,%2,%3};"
        : "+f"(d[0]), "+f"(d[1]), "+f"(d[2]), "+f"(d[3])
        : "r"(a0), "r"(a1), "r"(a2), "r"(a3), "r"(b0), "r"(b1));
}

__global__ __launch_bounds__(128, 1) void gemm_kernel(
    const float* __restrict__ x,
    const float* __restrict__ bvec,
    float* __restrict__ out)
{
    extern __shared__ float sm[];
    const int tid  = threadIdx.x;
    const int wid  = tid >> 5;
    const int lane = tid & 31;
    const int gid  = lane >> 2;   // 0..7
    const int tg   = lane & 3;    // 0..3
    const int bn = blockIdx.x;    // 0..7
    const int bm = blockIdx.y;    // 0..127
    const int wm = wid & 1;       // warp row -> 64 rows
    const int wn = wid >> 1;      // warp col -> 64 cols

    const uint32_t sbase = smem_u32(sm);

    // ---- ldmatrix per-lane base offsets (bytes within a stage) ----
    const int lg = lane >> 3;     // tile index within x4 (0..3)
    const int lr = lane & 7;      // row within tile
    // A: tiles {rows +0/+8} x {cols +0/+4}: row off = (lg&1)*8, col off = (lg>>1)*4
    const uint32_t a_off = (uint32_t)(((wm * 64 + (lg & 1) * 8 + lr) * SA
                                       + (lg >> 1) * 4) * 4);
    // B: tiles {n +0/+8} x {k +0/+4}: n off = (lg>>1)*8, k off = (lg&1)*4
    const uint32_t b_off = (uint32_t)((128 * SA + (wn * 64 + (lg >> 1) * 8 + lr) * SA
                                       + (lg & 1) * 4) * 4);

    auto load_chunk = [&](int c, int s) {
        const uint32_t st = sbase + (uint32_t)(s * STAGE_F * 4);
#pragma unroll
        for (int i = 0; i < 16; ++i) {
            int o = tid + i * 128;
            if (o < 1024) {               // A tile
                int r = o >> 3, seg = o & 7;
                cp_async16(st + (uint32_t)(r * SA + seg * 4) * 4,
                           x + (size_t)(bm * BM + r) * NN + c * BK + seg * 4);
            } else {                      // B tile
                int o2 = o - 1024;
                int n = o2 >> 3, seg = o2 & 7;
                cp_async16(st + (uint32_t)(128 * SA + n * SA + seg * 4) * 4,
                           g_Bt + (size_t)(bn * BN + n) * NN + c * BK + seg * 4);
            }
        }
        cp_commit();
    };

    float acc[4][8][4];
#pragma unroll
    for (int mt = 0; mt < 4; ++mt)
#pragma unroll
        for (int nt = 0; nt < 8; ++nt)
#pragma unroll
            for (int r = 0; r < 4; ++r) acc[mt][nt][r] = 0.0f;

    load_chunk(0, 0);
    load_chunk(1, 1);

#pragma unroll 1
    for (int c = 0; c < NCH; ++c) {
        cp_wait<1>();
        __syncthreads();
        {   // prefetch chunk c+2 (clamped; redundant tail loads are harmless)
            int cn = (c + 2 < NCH) ? (c + 2) : (NCH - 1);
            load_chunk(cn, (c + 2) % NSTAGE);
        }
        const uint32_t st = sbase + (uint32_t)((c % NSTAGE) * STAGE_F * 4);
        const uint32_t aB = st + a_off;
        const uint32_t bB = st + b_off;

#pragma unroll
        for (int ks = 0; ks < 4; ++ks) {
            const uint32_t kby = (uint32_t)(ks * 8 * 4);
            // B fragments: 8 nt -> 4 ldmatrix.x4 (2 nt each)
            uint32_t breg[8][2];
#pragma unroll
            for (int np = 0; np < 4; ++np) {
                uint32_t r[4];
                ldsm_x4(r, bB + kby + (uint32_t)(np * 16 * SA * 4));
                breg[np * 2 + 0][0] = r[0];
                breg[np * 2 + 0][1] = r[1];
                breg[np * 2 + 1][0] = r[2];
                breg[np * 2 + 1][1] = r[3];
            }
#pragma unroll
            for (int mt = 0; mt < 4; ++mt) {
                uint32_t a[4];
                ldsm_x4(a, aB + kby + (uint32_t)(mt * 16 * SA * 4));
                a[0] = cvt_rna_u(a[0]);
                a[1] = cvt_rna_u(a[1]);
                a[2] = cvt_rna_u(a[2]);
                a[3] = cvt_rna_u(a[3]);
#pragma unroll
                for (int nt = 0; nt < 8; ++nt)
                    mma_tf32(acc[mt][nt], a[0], a[1], a[2], a[3],
                             breg[nt][0], breg[nt][1]);
            }
        }
    }

    // ---- epilogue: D + bias -> out ----
    const float* brow = bvec + bn * BN + wn * 64;
#pragma unroll
    for (int mt = 0; mt < 4; ++mt) {
#pragma unroll
        for (int h = 0; h < 2; ++h) {
            const int r = bm * BM + wm * 64 + mt * 16 + gid + h * 8;
            float* orow = out + (size_t)r * NN + bn * BN + wn * 64;
#pragma unroll
            for (int nt = 0; nt < 8; ++nt) {
                const int cc = nt * 8 + tg * 2;
                float2 bb = __ldg((const float2*)(brow + cc));
                float2 o;
                o.x = acc[mt][nt][h * 2 + 0] + bb.x;
                o.y = acc[mt][nt][h * 2 + 1] + bb.y;
                *(float2*)(orow + cc) = o;
            }
        }
    }
}

// ============================================================================
extern "C" void kernel_launch(void* const* d_in, const int* in_sizes, int n_in,
                              void* d_out, int out_size) {
    const float* x          = (const float*)d_in[0];
    const float* perm_logit = (const float*)d_in[1];
    const float* abcd       = (const float*)d_in[2];
    const float* bvec       = (const float*)d_in[3];
    float* out = (float*)d_out;

    cudaFuncSetAttribute(gemm_kernel, cudaFuncAttributeMaxDynamicSharedMemorySize, DYN_SMEM);

    butterfly_identity_kernel<<<NN, 512>>>(perm_logit, abcd);
    {
        dim3 g(NN / 32, NN / 32);
        transpose_round_kernel<<<g, 256>>>();
    }
    {
        dim3 g(NN / BN, BB / BM);   // (8, 128): bn fastest for L2 reuse
        gemm_kernel<<<g, 128, DYN_SMEM>>>(x, bvec, out);
    }
}